// round 2
// baseline (speedup 1.0000x reference)
#include <cuda_runtime.h>
#include <cuda_bf16.h>
#include <math.h>

#define N_TOK 4096
#define DIM   768
#define NH    12
#define HD    64
#define SCALE 0.125f   // 1/sqrt(64)

// Scratch (allocation-free rule: device globals)
__device__ float g_q[NH * N_TOK * HD];
__device__ float g_k[NH * N_TOK * HD];
__device__ float g_v[NH * N_TOK * HD];
__device__ float g_att[N_TOK * DIM];

// ---------------------------------------------------------------------------
// Kernel 1: qkv = x @ w_qkv^T, scattered into head-major Q/K/V
// A: [4096][768] row-major, W: [2304][768] row-major. C[m][c] = dot(A[m], W[c])
// 128x128 tile, BK=16, 256 threads, 8x8 per thread.
// ---------------------------------------------------------------------------
__global__ __launch_bounds__(256) void sgemm_qkv(const float* __restrict__ A,
                                                 const float* __restrict__ W) {
    __shared__ float As[16][128];
    __shared__ float Bs[16][128];
    const int bm = blockIdx.y * 128;
    const int bn = blockIdx.x * 128;
    const int tid = threadIdx.x;
    const int lr = tid >> 1;          // 0..127
    const int lc = (tid & 1) << 3;    // 0 or 8
    const int ty = tid >> 4;          // 0..15
    const int tx = tid & 15;          // 0..15

    float acc[8][8];
#pragma unroll
    for (int i = 0; i < 8; i++)
#pragma unroll
        for (int j = 0; j < 8; j++) acc[i][j] = 0.f;

    for (int k0 = 0; k0 < DIM; k0 += 16) {
        float4 a0 = *(const float4*)(A + (size_t)(bm + lr) * DIM + k0 + lc);
        float4 a1 = *(const float4*)(A + (size_t)(bm + lr) * DIM + k0 + lc + 4);
        float4 b0 = *(const float4*)(W + (size_t)(bn + lr) * DIM + k0 + lc);
        float4 b1 = *(const float4*)(W + (size_t)(bn + lr) * DIM + k0 + lc + 4);
        __syncthreads();
        As[lc + 0][lr] = a0.x; As[lc + 1][lr] = a0.y;
        As[lc + 2][lr] = a0.z; As[lc + 3][lr] = a0.w;
        As[lc + 4][lr] = a1.x; As[lc + 5][lr] = a1.y;
        As[lc + 6][lr] = a1.z; As[lc + 7][lr] = a1.w;
        Bs[lc + 0][lr] = b0.x; Bs[lc + 1][lr] = b0.y;
        Bs[lc + 2][lr] = b0.z; Bs[lc + 3][lr] = b0.w;
        Bs[lc + 4][lr] = b1.x; Bs[lc + 5][lr] = b1.y;
        Bs[lc + 6][lr] = b1.z; Bs[lc + 7][lr] = b1.w;
        __syncthreads();
#pragma unroll
        for (int kk = 0; kk < 16; kk++) {
            float ar[8], br[8];
#pragma unroll
            for (int i = 0; i < 8; i++) ar[i] = As[kk][ty * 8 + i];
#pragma unroll
            for (int j = 0; j < 8; j++) br[j] = Bs[kk][tx * 8 + j];
#pragma unroll
            for (int i = 0; i < 8; i++)
#pragma unroll
                for (int j = 0; j < 8; j++) acc[i][j] += ar[i] * br[j];
        }
    }

    // Scatter into q/k/v: col c -> (s = c/768, h = (c%768)/64, d = c%64)
#pragma unroll
    for (int i = 0; i < 8; i++) {
        int m = bm + ty * 8 + i;
#pragma unroll
        for (int j = 0; j < 8; j++) {
            int c = bn + tx * 8 + j;
            int s = c / DIM;
            int rem = c - s * DIM;
            int h = rem >> 6;
            int d = rem & 63;
            float* dst = (s == 0) ? g_q : (s == 1) ? g_k : g_v;
            dst[((size_t)h * N_TOK + m) * HD + d] = acc[i][j];
        }
    }
}

// ---------------------------------------------------------------------------
// Kernel 2: flash attention (online softmax), fp32.
// grid: (N_TOK/64, NH), 256 threads.
// Each block: 64 queries of one head. Key blocks of 32.
// Thread (qp = tid/8, cl = tid%8): 2 q-rows (2*qp, 2*qp+1), key cols cl+8t,
// output cols cl+8u.
// ---------------------------------------------------------------------------
__global__ __launch_bounds__(256) void flash_attn_kernel() {
    __shared__ float sQ[64][65];
    __shared__ float sK[32][65];
    __shared__ float sV[32][65];
    __shared__ float sP[64][33];

    const int h  = blockIdx.y;
    const int q0 = blockIdx.x * 64;
    const int tid = threadIdx.x;
    const int qp = tid >> 3;          // 0..31
    const int cl = tid & 7;           // 0..7
    const int qr0 = qp * 2;
    const int qr1 = qp * 2 + 1;

    const float* Qh = g_q + (size_t)h * N_TOK * HD;
    const float* Kh = g_k + (size_t)h * N_TOK * HD;
    const float* Vh = g_v + (size_t)h * N_TOK * HD;

    // Load Q tile: 64x64 = 1024 float4
    for (int i = tid; i < 1024; i += 256) {
        int r = i >> 4;
        int c = (i & 15) << 2;
        float4 t = *(const float4*)(Qh + (size_t)(q0 + r) * HD + c);
        sQ[r][c] = t.x; sQ[r][c + 1] = t.y; sQ[r][c + 2] = t.z; sQ[r][c + 3] = t.w;
    }

    float m0 = -INFINITY, m1 = -INFINITY;
    float l0 = 0.f, l1 = 0.f;
    float o0[8], o1[8];
#pragma unroll
    for (int u = 0; u < 8; u++) { o0[u] = 0.f; o1[u] = 0.f; }

    for (int kb = 0; kb < N_TOK; kb += 32) {
        __syncthreads();   // previous PV done before reloading K/V
        // load K,V tiles: 32x64 = 512 float4 each
        for (int i = tid; i < 512; i += 256) {
            int r = i >> 4;
            int c = (i & 15) << 2;
            float4 t = *(const float4*)(Kh + (size_t)(kb + r) * HD + c);
            sK[r][c] = t.x; sK[r][c + 1] = t.y; sK[r][c + 2] = t.z; sK[r][c + 3] = t.w;
            float4 u4 = *(const float4*)(Vh + (size_t)(kb + r) * HD + c);
            sV[r][c] = u4.x; sV[r][c + 1] = u4.y; sV[r][c + 2] = u4.z; sV[r][c + 3] = u4.w;
        }
        __syncthreads();

        // S = Q K^T for 2 q-rows x 4 key cols
        float s0[4] = {0.f, 0.f, 0.f, 0.f};
        float s1[4] = {0.f, 0.f, 0.f, 0.f};
#pragma unroll 16
        for (int kd = 0; kd < 64; kd++) {
            float qv0 = sQ[qr0][kd];
            float qv1 = sQ[qr1][kd];
#pragma unroll
            for (int t = 0; t < 4; t++) {
                float kv = sK[cl + 8 * t][kd];
                s0[t] += qv0 * kv;
                s1[t] += qv1 * kv;
            }
        }
#pragma unroll
        for (int t = 0; t < 4; t++) { s0[t] *= SCALE; s1[t] *= SCALE; }

        // online softmax
        float mx0 = fmaxf(fmaxf(s0[0], s0[1]), fmaxf(s0[2], s0[3]));
        float mx1 = fmaxf(fmaxf(s1[0], s1[1]), fmaxf(s1[2], s1[3]));
#pragma unroll
        for (int off = 1; off < 8; off <<= 1) {
            mx0 = fmaxf(mx0, __shfl_xor_sync(0xffffffffu, mx0, off));
            mx1 = fmaxf(mx1, __shfl_xor_sync(0xffffffffu, mx1, off));
        }
        float mn0 = fmaxf(m0, mx0);
        float mn1 = fmaxf(m1, mx1);
        float a0 = __expf(m0 - mn0);
        float a1 = __expf(m1 - mn1);
        float ls0 = 0.f, ls1 = 0.f;
#pragma unroll
        for (int t = 0; t < 4; t++) {
            float p0 = __expf(s0[t] - mn0);
            float p1 = __expf(s1[t] - mn1);
            ls0 += p0; ls1 += p1;
            sP[qr0][cl + 8 * t] = p0;
            sP[qr1][cl + 8 * t] = p1;
        }
#pragma unroll
        for (int off = 1; off < 8; off <<= 1) {
            ls0 += __shfl_xor_sync(0xffffffffu, ls0, off);
            ls1 += __shfl_xor_sync(0xffffffffu, ls1, off);
        }
        l0 = l0 * a0 + ls0;
        l1 = l1 * a1 + ls1;
        m0 = mn0; m1 = mn1;
#pragma unroll
        for (int u = 0; u < 8; u++) { o0[u] *= a0; o1[u] *= a1; }

        __syncwarp();   // sP rows of this q-group are warp-local

        // O += P V
#pragma unroll 8
        for (int j = 0; j < 32; j++) {
            float p0 = sP[qr0][j];
            float p1 = sP[qr1][j];
#pragma unroll
            for (int u = 0; u < 8; u++) {
                float vv = sV[j][cl + 8 * u];
                o0[u] += p0 * vv;
                o1[u] += p1 * vv;
            }
        }
    }

    float inv0 = 1.f / l0;
    float inv1 = 1.f / l1;
#pragma unroll
    for (int u = 0; u < 8; u++) {
        int d = cl + 8 * u;
        g_att[(size_t)(q0 + qr0) * DIM + h * HD + d] = o0[u] * inv0;
        g_att[(size_t)(q0 + qr1) * DIM + h * HD + d] = o1[u] * inv1;
    }
}

// ---------------------------------------------------------------------------
// Kernel 3: out = att @ w_proj^T + b_proj
// ---------------------------------------------------------------------------
__global__ __launch_bounds__(256) void sgemm_proj(const float* __restrict__ W,
                                                  const float* __restrict__ bias,
                                                  float* __restrict__ out) {
    __shared__ float As[16][128];
    __shared__ float Bs[16][128];
    const int bm = blockIdx.y * 128;
    const int bn = blockIdx.x * 128;
    const int tid = threadIdx.x;
    const int lr = tid >> 1;
    const int lc = (tid & 1) << 3;
    const int ty = tid >> 4;
    const int tx = tid & 15;
    const float* A = g_att;

    float acc[8][8];
#pragma unroll
    for (int i = 0; i < 8; i++)
#pragma unroll
        for (int j = 0; j < 8; j++) acc[i][j] = 0.f;

    for (int k0 = 0; k0 < DIM; k0 += 16) {
        float4 a0 = *(const float4*)(A + (size_t)(bm + lr) * DIM + k0 + lc);
        float4 a1 = *(const float4*)(A + (size_t)(bm + lr) * DIM + k0 + lc + 4);
        float4 b0 = *(const float4*)(W + (size_t)(bn + lr) * DIM + k0 + lc);
        float4 b1 = *(const float4*)(W + (size_t)(bn + lr) * DIM + k0 + lc + 4);
        __syncthreads();
        As[lc + 0][lr] = a0.x; As[lc + 1][lr] = a0.y;
        As[lc + 2][lr] = a0.z; As[lc + 3][lr] = a0.w;
        As[lc + 4][lr] = a1.x; As[lc + 5][lr] = a1.y;
        As[lc + 6][lr] = a1.z; As[lc + 7][lr] = a1.w;
        Bs[lc + 0][lr] = b0.x; Bs[lc + 1][lr] = b0.y;
        Bs[lc + 2][lr] = b0.z; Bs[lc + 3][lr] = b0.w;
        Bs[lc + 4][lr] = b1.x; Bs[lc + 5][lr] = b1.y;
        Bs[lc + 6][lr] = b1.z; Bs[lc + 7][lr] = b1.w;
        __syncthreads();
#pragma unroll
        for (int kk = 0; kk < 16; kk++) {
            float ar[8], br[8];
#pragma unroll
            for (int i = 0; i < 8; i++) ar[i] = As[kk][ty * 8 + i];
#pragma unroll
            for (int j = 0; j < 8; j++) br[j] = Bs[kk][tx * 8 + j];
#pragma unroll
            for (int i = 0; i < 8; i++)
#pragma unroll
                for (int j = 0; j < 8; j++) acc[i][j] += ar[i] * br[j];
        }
    }

#pragma unroll
    for (int i = 0; i < 8; i++) {
        int m = bm + ty * 8 + i;
#pragma unroll
        for (int j = 0; j < 8; j++) {
            int c = bn + tx * 8 + j;
            out[(size_t)m * DIM + c] = acc[i][j] + bias[c];
        }
    }
}

// ---------------------------------------------------------------------------
extern "C" void kernel_launch(void* const* d_in, const int* in_sizes, int n_in,
                              void* d_out, int out_size) {
    const float* x      = (const float*)d_in[0];   // [4096, 768]
    const float* w_qkv  = (const float*)d_in[1];   // [2304, 768]
    const float* w_proj = (const float*)d_in[2];   // [768, 768]
    const float* b_proj = (const float*)d_in[3];   // [768]
    float* out = (float*)d_out;                    // [4096, 768]

    {
        dim3 grid(2304 / 128, N_TOK / 128);
        sgemm_qkv<<<grid, 256>>>(x, w_qkv);
    }
    {
        dim3 grid(N_TOK / 64, NH);
        flash_attn_kernel<<<grid, 256>>>();
    }
    {
        dim3 grid(DIM / 128, N_TOK / 128);
        sgemm_proj<<<grid, 256>>>(w_proj, b_proj, out);
    }
}

// round 3
// speedup vs baseline: 4.6908x; 4.6908x over previous
#include <cuda_runtime.h>
#include <cuda_bf16.h>
#include <math.h>
#include <stdint.h>

#define N_TOK 4096
#define DIM   768
#define NH    12
#define HD    64
#define SCALE 0.125f   // 1/sqrt(64)

// Scratch (allocation-free rule: device globals)
__device__ float g_q[NH * N_TOK * HD];
__device__ float g_k[NH * N_TOK * HD];
__device__ float g_v[NH * N_TOK * HD];
__device__ float g_att[N_TOK * DIM];

// ---------------------------------------------------------------------------
// helpers
// ---------------------------------------------------------------------------
__device__ __forceinline__ uint32_t f2tf(float f) {
    uint32_t r;
    asm("cvt.rna.tf32.f32 %0, %1;" : "=r"(r) : "f"(f));
    return r;
}

__device__ __forceinline__ void mma_tf32(float& c0, float& c1, float& c2, float& c3,
                                         uint32_t a0, uint32_t a1, uint32_t a2, uint32_t a3,
                                         uint32_t b0, uint32_t b1) {
    asm volatile("mma.sync.aligned.m16n8k8.row.col.f32.tf32.tf32.f32 "
                 "{%0,%1,%2,%3}, {%4,%5,%6,%7}, {%8,%9}, {%0,%1,%2,%3};"
                 : "+f"(c0), "+f"(c1), "+f"(c2), "+f"(c3)
                 : "r"(a0), "r"(a1), "r"(a2), "r"(a3), "r"(b0), "r"(b1));
}

__device__ __forceinline__ void qkv_scatter(int m, int c, float v) {
    int s = c / DIM;
    int rem = c - s * DIM;
    int h = rem >> 6;
    int d = rem & 63;
    float* dst = (s == 0) ? g_q : (s == 1) ? g_k : g_v;
    dst[((size_t)h * N_TOK + m) * HD + d] = v;
}

// ---------------------------------------------------------------------------
// Kernel 1: qkv = x @ w_qkv^T  (tf32 mma), scatter into head-major Q/K/V
// C[m][n] = sum_k A[m][k] * W[n][k].  BM=128, BN=128, BK=32, 256 thr, 8 warps.
// Warp grid 2(m) x 4(n): warp tile 64x32. mma tiles 4x4 per warp.
// smem stride 36 words: frag loads conflict-free ((4*row + k) covers all banks).
// ---------------------------------------------------------------------------
__global__ __launch_bounds__(256) void qkv_mma_kernel(const float* __restrict__ A,
                                                      const float* __restrict__ W) {
    __shared__ uint32_t sA[128 * 36];
    __shared__ uint32_t sB[128 * 36];
    const int bm = blockIdx.y * 128;
    const int bn = blockIdx.x * 128;
    const int tid = threadIdx.x;
    const int wid = tid >> 5;
    const int lane = tid & 31;
    const int gid = lane >> 2;
    const int tig = lane & 3;
    const int wm = wid >> 2;   // 0..1
    const int wn = wid & 3;    // 0..3

    float acc[4][4][4];
#pragma unroll
    for (int mi = 0; mi < 4; mi++)
#pragma unroll
        for (int ni = 0; ni < 4; ni++)
#pragma unroll
            for (int t = 0; t < 4; t++) acc[mi][ni][t] = 0.f;

    const int lr = tid >> 3;          // 0..31 (row step base)
    const int lc = (tid & 7) << 2;    // 0,4,...,28

    for (int k0 = 0; k0 < DIM; k0 += 32) {
        float4 av[4], bv[4];
#pragma unroll
        for (int i = 0; i < 4; i++) {
            int r = lr + i * 32;
            av[i] = *(const float4*)(A + (size_t)(bm + r) * DIM + k0 + lc);
            bv[i] = *(const float4*)(W + (size_t)(bn + r) * DIM + k0 + lc);
        }
        __syncthreads();
#pragma unroll
        for (int i = 0; i < 4; i++) {
            int r = lr + i * 32;
            uint4 pa = make_uint4(f2tf(av[i].x), f2tf(av[i].y), f2tf(av[i].z), f2tf(av[i].w));
            uint4 pb = make_uint4(f2tf(bv[i].x), f2tf(bv[i].y), f2tf(bv[i].z), f2tf(bv[i].w));
            *(uint4*)(sA + r * 36 + lc) = pa;
            *(uint4*)(sB + r * 36 + lc) = pb;
        }
        __syncthreads();

#pragma unroll
        for (int ks = 0; ks < 4; ks++) {
            const int kk = ks * 8;
            uint32_t af[4][4];
#pragma unroll
            for (int mi = 0; mi < 4; mi++) {
                int row = wm * 64 + mi * 16 + gid;
                af[mi][0] = sA[row * 36 + kk + tig];
                af[mi][1] = sA[(row + 8) * 36 + kk + tig];
                af[mi][2] = sA[row * 36 + kk + tig + 4];
                af[mi][3] = sA[(row + 8) * 36 + kk + tig + 4];
            }
            uint32_t bf[4][2];
#pragma unroll
            for (int ni = 0; ni < 4; ni++) {
                int n = wn * 32 + ni * 8 + gid;
                bf[ni][0] = sB[n * 36 + kk + tig];
                bf[ni][1] = sB[n * 36 + kk + tig + 4];
            }
#pragma unroll
            for (int mi = 0; mi < 4; mi++)
#pragma unroll
                for (int ni = 0; ni < 4; ni++)
                    mma_tf32(acc[mi][ni][0], acc[mi][ni][1], acc[mi][ni][2], acc[mi][ni][3],
                             af[mi][0], af[mi][1], af[mi][2], af[mi][3],
                             bf[ni][0], bf[ni][1]);
        }
    }

#pragma unroll
    for (int mi = 0; mi < 4; mi++) {
        int r = bm + wm * 64 + mi * 16 + gid;
#pragma unroll
        for (int ni = 0; ni < 4; ni++) {
            int c = bn + wn * 32 + ni * 8 + 2 * tig;
            qkv_scatter(r, c, acc[mi][ni][0]);
            qkv_scatter(r, c + 1, acc[mi][ni][1]);
            qkv_scatter(r + 8, c, acc[mi][ni][2]);
            qkv_scatter(r + 8, c + 1, acc[mi][ni][3]);
        }
    }
}

// ---------------------------------------------------------------------------
// Kernel 2: flash attention, tf32 mma.
// grid (4096/128, 12), 256 threads (8 warps). Each warp: 16 q-rows.
// Key tiles of 64. Q held in registers as tf32 A-fragments.
// smem (dynamic): sK[64][68], sV[64][72], sP[128][68]  (uint32 tf32 bits)
// ---------------------------------------------------------------------------
#define SKS 68
#define SVS 72
#define SPS 68
#define FLASH_SMEM ((64 * SKS + 64 * SVS + 128 * SPS) * 4)

__global__ __launch_bounds__(256) void flash_mma_kernel() {
    extern __shared__ uint32_t smem[];
    uint32_t* sK = smem;                        // [64][SKS]
    uint32_t* sV = smem + 64 * SKS;             // [64][SVS]
    uint32_t* sP = smem + 64 * SKS + 64 * SVS;  // [128][SPS]

    const int h = blockIdx.y;
    const int q0 = blockIdx.x * 128;
    const int tid = threadIdx.x;
    const int wid = tid >> 5;
    const int lane = tid & 31;
    const int gid = lane >> 2;
    const int tig = lane & 3;

    const float* Qh = g_q + (size_t)h * N_TOK * HD;
    const float* Kh = g_k + (size_t)h * N_TOK * HD;
    const float* Vh = g_v + (size_t)h * N_TOK * HD;

    // Q fragments in registers (pre-scaled by 1/sqrt(hd))
    const int qrow = q0 + wid * 16 + gid;
    uint32_t qa[8][4];
#pragma unroll
    for (int kt = 0; kt < 8; kt++) {
        int c = kt * 8 + tig;
        qa[kt][0] = f2tf(Qh[(size_t)qrow * HD + c] * SCALE);
        qa[kt][1] = f2tf(Qh[(size_t)(qrow + 8) * HD + c] * SCALE);
        qa[kt][2] = f2tf(Qh[(size_t)qrow * HD + c + 4] * SCALE);
        qa[kt][3] = f2tf(Qh[(size_t)(qrow + 8) * HD + c + 4] * SCALE);
    }

    float m0 = -INFINITY, m1 = -INFINITY, l0 = 0.f, l1 = 0.f;
    float o[8][4];
#pragma unroll
    for (int nt = 0; nt < 8; nt++)
#pragma unroll
        for (int t = 0; t < 4; t++) o[nt][t] = 0.f;

    const int lrow = tid >> 4;          // 0..15
    const int lcol = (tid & 15) << 2;   // 0..60

    for (int kb = 0; kb < N_TOK; kb += 64) {
        __syncthreads();
        // load K,V tile 64x64 each
#pragma unroll
        for (int i = 0; i < 4; i++) {
            int r = lrow + i * 16;
            float4 kv = *(const float4*)(Kh + (size_t)(kb + r) * HD + lcol);
            float4 vv = *(const float4*)(Vh + (size_t)(kb + r) * HD + lcol);
            *(uint4*)(sK + r * SKS + lcol) =
                make_uint4(f2tf(kv.x), f2tf(kv.y), f2tf(kv.z), f2tf(kv.w));
            *(uint4*)(sV + r * SVS + lcol) =
                make_uint4(f2tf(vv.x), f2tf(vv.y), f2tf(vv.z), f2tf(vv.w));
        }
        __syncthreads();

        // S = Q K^T  (16 x 64 per warp)
        float s[8][4];
#pragma unroll
        for (int nt = 0; nt < 8; nt++)
#pragma unroll
            for (int t = 0; t < 4; t++) s[nt][t] = 0.f;
#pragma unroll
        for (int kt = 0; kt < 8; kt++) {
#pragma unroll
            for (int nt = 0; nt < 8; nt++) {
                uint32_t b0 = sK[(nt * 8 + gid) * SKS + kt * 8 + tig];
                uint32_t b1 = sK[(nt * 8 + gid) * SKS + kt * 8 + tig + 4];
                mma_tf32(s[nt][0], s[nt][1], s[nt][2], s[nt][3],
                         qa[kt][0], qa[kt][1], qa[kt][2], qa[kt][3], b0, b1);
            }
        }

        // online softmax (rows gid and gid+8 of this warp's 16 rows)
        float mx0 = -INFINITY, mx1 = -INFINITY;
#pragma unroll
        for (int nt = 0; nt < 8; nt++) {
            mx0 = fmaxf(mx0, fmaxf(s[nt][0], s[nt][1]));
            mx1 = fmaxf(mx1, fmaxf(s[nt][2], s[nt][3]));
        }
#pragma unroll
        for (int off = 1; off < 4; off <<= 1) {
            mx0 = fmaxf(mx0, __shfl_xor_sync(0xffffffffu, mx0, off));
            mx1 = fmaxf(mx1, __shfl_xor_sync(0xffffffffu, mx1, off));
        }
        float mn0 = fmaxf(m0, mx0);
        float mn1 = fmaxf(m1, mx1);
        float a0 = __expf(m0 - mn0);
        float a1 = __expf(m1 - mn1);
        float ls0 = 0.f, ls1 = 0.f;
        const int prow = wid * 16 + gid;
#pragma unroll
        for (int nt = 0; nt < 8; nt++) {
            float p0 = __expf(s[nt][0] - mn0);
            float p1 = __expf(s[nt][1] - mn0);
            float p2 = __expf(s[nt][2] - mn1);
            float p3 = __expf(s[nt][3] - mn1);
            ls0 += p0 + p1;
            ls1 += p2 + p3;
            int c = nt * 8 + 2 * tig;
            sP[prow * SPS + c] = f2tf(p0);
            sP[prow * SPS + c + 1] = f2tf(p1);
            sP[(prow + 8) * SPS + c] = f2tf(p2);
            sP[(prow + 8) * SPS + c + 1] = f2tf(p3);
        }
#pragma unroll
        for (int off = 1; off < 4; off <<= 1) {
            ls0 += __shfl_xor_sync(0xffffffffu, ls0, off);
            ls1 += __shfl_xor_sync(0xffffffffu, ls1, off);
        }
        m0 = mn0; m1 = mn1;
        l0 = l0 * a0 + ls0;
        l1 = l1 * a1 + ls1;
#pragma unroll
        for (int nt = 0; nt < 8; nt++) {
            o[nt][0] *= a0; o[nt][1] *= a0;
            o[nt][2] *= a1; o[nt][3] *= a1;
        }
        __syncwarp();

        // O += P V   (A = P from sP, B = V from sV)
#pragma unroll
        for (int kt = 0; kt < 8; kt++) {
            uint32_t pa0 = sP[prow * SPS + kt * 8 + tig];
            uint32_t pa1 = sP[(prow + 8) * SPS + kt * 8 + tig];
            uint32_t pa2 = sP[prow * SPS + kt * 8 + tig + 4];
            uint32_t pa3 = sP[(prow + 8) * SPS + kt * 8 + tig + 4];
#pragma unroll
            for (int nt = 0; nt < 8; nt++) {
                uint32_t b0 = sV[(kt * 8 + tig) * SVS + nt * 8 + gid];
                uint32_t b1 = sV[(kt * 8 + tig + 4) * SVS + nt * 8 + gid];
                mma_tf32(o[nt][0], o[nt][1], o[nt][2], o[nt][3],
                         pa0, pa1, pa2, pa3, b0, b1);
            }
        }
    }

    float inv0 = 1.f / l0;
    float inv1 = 1.f / l1;
    const int orow = q0 + wid * 16 + gid;
#pragma unroll
    for (int nt = 0; nt < 8; nt++) {
        int c = h * HD + nt * 8 + 2 * tig;
        g_att[(size_t)orow * DIM + c] = o[nt][0] * inv0;
        g_att[(size_t)orow * DIM + c + 1] = o[nt][1] * inv0;
        g_att[(size_t)(orow + 8) * DIM + c] = o[nt][2] * inv1;
        g_att[(size_t)(orow + 8) * DIM + c + 1] = o[nt][3] * inv1;
    }
}

// ---------------------------------------------------------------------------
// Kernel 3: out = att @ w_proj^T + b_proj  (tf32 mma), same structure as K1.
// ---------------------------------------------------------------------------
__global__ __launch_bounds__(256) void proj_mma_kernel(const float* __restrict__ W,
                                                       const float* __restrict__ bias,
                                                       float* __restrict__ out) {
    __shared__ uint32_t sA[128 * 36];
    __shared__ uint32_t sB[128 * 36];
    const int bm = blockIdx.y * 128;
    const int bn = blockIdx.x * 128;
    const int tid = threadIdx.x;
    const int wid = tid >> 5;
    const int lane = tid & 31;
    const int gid = lane >> 2;
    const int tig = lane & 3;
    const int wm = wid >> 2;
    const int wn = wid & 3;
    const float* A = g_att;

    float acc[4][4][4];
#pragma unroll
    for (int mi = 0; mi < 4; mi++)
#pragma unroll
        for (int ni = 0; ni < 4; ni++)
#pragma unroll
            for (int t = 0; t < 4; t++) acc[mi][ni][t] = 0.f;

    const int lr = tid >> 3;
    const int lc = (tid & 7) << 2;

    for (int k0 = 0; k0 < DIM; k0 += 32) {
        float4 av[4], bv[4];
#pragma unroll
        for (int i = 0; i < 4; i++) {
            int r = lr + i * 32;
            av[i] = *(const float4*)(A + (size_t)(bm + r) * DIM + k0 + lc);
            bv[i] = *(const float4*)(W + (size_t)(bn + r) * DIM + k0 + lc);
        }
        __syncthreads();
#pragma unroll
        for (int i = 0; i < 4; i++) {
            int r = lr + i * 32;
            *(uint4*)(sA + r * 36 + lc) =
                make_uint4(f2tf(av[i].x), f2tf(av[i].y), f2tf(av[i].z), f2tf(av[i].w));
            *(uint4*)(sB + r * 36 + lc) =
                make_uint4(f2tf(bv[i].x), f2tf(bv[i].y), f2tf(bv[i].z), f2tf(bv[i].w));
        }
        __syncthreads();

#pragma unroll
        for (int ks = 0; ks < 4; ks++) {
            const int kk = ks * 8;
            uint32_t af[4][4];
#pragma unroll
            for (int mi = 0; mi < 4; mi++) {
                int row = wm * 64 + mi * 16 + gid;
                af[mi][0] = sA[row * 36 + kk + tig];
                af[mi][1] = sA[(row + 8) * 36 + kk + tig];
                af[mi][2] = sA[row * 36 + kk + tig + 4];
                af[mi][3] = sA[(row + 8) * 36 + kk + tig + 4];
            }
            uint32_t bf[4][2];
#pragma unroll
            for (int ni = 0; ni < 4; ni++) {
                int n = wn * 32 + ni * 8 + gid;
                bf[ni][0] = sB[n * 36 + kk + tig];
                bf[ni][1] = sB[n * 36 + kk + tig + 4];
            }
#pragma unroll
            for (int mi = 0; mi < 4; mi++)
#pragma unroll
                for (int ni = 0; ni < 4; ni++)
                    mma_tf32(acc[mi][ni][0], acc[mi][ni][1], acc[mi][ni][2], acc[mi][ni][3],
                             af[mi][0], af[mi][1], af[mi][2], af[mi][3],
                             bf[ni][0], bf[ni][1]);
        }
    }

#pragma unroll
    for (int mi = 0; mi < 4; mi++) {
        int r = bm + wm * 64 + mi * 16 + gid;
#pragma unroll
        for (int ni = 0; ni < 4; ni++) {
            int c = bn + wn * 32 + ni * 8 + 2 * tig;
            out[(size_t)r * DIM + c]       = acc[mi][ni][0] + bias[c];
            out[(size_t)r * DIM + c + 1]   = acc[mi][ni][1] + bias[c + 1];
            out[(size_t)(r + 8) * DIM + c]     = acc[mi][ni][2] + bias[c];
            out[(size_t)(r + 8) * DIM + c + 1] = acc[mi][ni][3] + bias[c + 1];
        }
    }
}

// ---------------------------------------------------------------------------
extern "C" void kernel_launch(void* const* d_in, const int* in_sizes, int n_in,
                              void* d_out, int out_size) {
    const float* x      = (const float*)d_in[0];   // [4096, 768]
    const float* w_qkv  = (const float*)d_in[1];   // [2304, 768]
    const float* w_proj = (const float*)d_in[2];   // [768, 768]
    const float* b_proj = (const float*)d_in[3];   // [768]
    float* out = (float*)d_out;                    // [4096, 768]

    static bool attr_set = false;
    if (!attr_set) {
        cudaFuncSetAttribute(flash_mma_kernel,
                             cudaFuncAttributeMaxDynamicSharedMemorySize, FLASH_SMEM);
        attr_set = true;
    }

    {
        dim3 grid(2304 / 128, N_TOK / 128);
        qkv_mma_kernel<<<grid, 256>>>(x, w_qkv);
    }
    {
        dim3 grid(N_TOK / 128, NH);
        flash_mma_kernel<<<grid, 256, FLASH_SMEM>>>();
    }
    {
        dim3 grid(DIM / 128, N_TOK / 128);
        proj_mma_kernel<<<grid, 256>>>(w_proj, b_proj, out);
    }
}